// round 14
// baseline (speedup 1.0000x reference)
#include <cuda_runtime.h>
#include <cuda_fp16.h>
#include <math.h>
#include <float.h>

#define BB 16
#define NN 1024
#define DD 5
#define RH 8
#define NWORDS 32            // 1024 bits / 32
#define ROWS (BB*NN)         // 16384
#define PACK_BLOCKS (ROWS/8)              // 2048 (8 warps/blk, 1 row/warp)
#define REC_BLOCKS  (ROWS/256)            // 64 (4 per batch)
#define LOG2E 1.4426950408889634f

// ---------------- scratch (static device globals; no runtime alloc) --------
// g_bits uses a PERMUTED bit layout (pack<->attn private):
//   row element e: chunk c=e>>7, lane=(e>>2)&31, k=e&3; word w'=c*4+k, bit=lane
//   decode: e = (w'>>2)*128 + bit*4 + (w'&3)
// g_kv/g_vc are stored at PERMUTED within-batch position
//   jp(i) = (i>>2) + (i&3)*256   (bijection on 0..1023)
// so that compacted gather indices cycle all 8 smem 16B bank-groups.
__device__ unsigned int g_bits[ROWS*NWORDS];   // packed 1-hop adjacency (2 MB)
__device__ uint4        g_kv[ROWS];            // fp16: (k0,k1)(k2,k3)(k4,v0)(v1,v2)
__device__ float4       g_vc[ROWS];            // .x = half2(v3,v4), .y..w = coors
__device__ uint4        g_qh[ROWS];            // half2: q01,q23,(q4,0); pre-scaled
__device__ float        g_part[BB*32*DD];      // per-CTA agg partial sums
__device__ float        g_fpart[REC_BLOCKS*DD];// per-REC-block feats partial sums
__device__ int          g_simple;              // rbias is linear in dist
__device__ float        g_C, g_bcShift;        // log2e-scaled slope / shifted bias

// ------- pack adjacency bitset + node tables + feats pooling + coeffs ------
// dtype probe (per pack block, same first 8KB -> L2-resident):
//   uint8 bools: nonzero at all byte offsets       -> fa=1, fb=1
//   int32 bools: nonzero only at offset%4==0       -> fa=1, fb=0
//   f32   bools: 1.0f bytes at offsets 2,3         -> fa=0, fb=1
// Pack: lane loads uint4/uchar4 (streaming, evict-first), 4 ballots per
// 128-element chunk form words in the permuted layout; coalesced store.
// REC blocks also reduce their 256 nodes' feats (fixed order) -> g_fpart,
// so the head kernel never streams the 320KB feats tensor.
__global__ void k_pack_rec(const unsigned* __restrict__ a,
                           const float* __restrict__ feats,
                           const float* __restrict__ coors,
                           const float* __restrict__ Wq,
                           const float* __restrict__ Wk,
                           const float* __restrict__ Wv,
                           const float* __restrict__ wr1,
                           const float* __restrict__ br1,
                           const float* __restrict__ wr2,
                           const float* __restrict__ br2) {
    const unsigned FULL = 0xffffffffu;
    if (blockIdx.x < PACK_BLOCKS) {
        __shared__ unsigned sFa, sFb;
        if (threadIdx.x == 0) { sFa = 0; sFb = 0; }
        __syncthreads();
        {
            const uchar4* p8 = (const uchar4*)a;
            unsigned fa = 0, fb = 0;
            #pragma unroll
            for (int k = 0; k < 8; k++) {
                uchar4 u = p8[threadIdx.x + k*256];
                fa |= u.x;
                fb |= (unsigned)(u.y | u.z | u.w);
            }
            if (fa) atomicOr(&sFa, 1u);
            if (fb) atomicOr(&sFb, 1u);
        }
        __syncthreads();
        bool u8 = sFa && sFb;

        int lane = threadIdx.x & 31;
        int grow = blockIdx.x * 8 + (threadIdx.x >> 5);   // row 0..16383
        unsigned myword = 0;
        if (u8) {
            const uchar4* a4 = (const uchar4*)a;
            #pragma unroll
            for (int c = 0; c < 8; c++) {
                unsigned raw = __ldcs((const unsigned*)(a4 + (size_t)grow*256 + c*32 + lane));
                unsigned w0 = __ballot_sync(FULL, (raw & 0x000000FFu) != 0);
                unsigned w1 = __ballot_sync(FULL, (raw & 0x0000FF00u) != 0);
                unsigned w2 = __ballot_sync(FULL, (raw & 0x00FF0000u) != 0);
                unsigned w3 = __ballot_sync(FULL, (raw & 0xFF000000u) != 0);
                if (lane == c*4+0) myword = w0;
                if (lane == c*4+1) myword = w1;
                if (lane == c*4+2) myword = w2;
                if (lane == c*4+3) myword = w3;
            }
        } else {
            const uint4* a4 = (const uint4*)a;
            #pragma unroll
            for (int c = 0; c < 8; c++) {
                uint4 u = __ldcs(a4 + (size_t)grow*256 + c*32 + lane);
                unsigned w0 = __ballot_sync(FULL, u.x != 0);
                unsigned w1 = __ballot_sync(FULL, u.y != 0);
                unsigned w2 = __ballot_sync(FULL, u.z != 0);
                unsigned w3 = __ballot_sync(FULL, u.w != 0);
                if (lane == c*4+0) myword = w0;
                if (lane == c*4+1) myword = w1;
                if (lane == c*4+2) myword = w2;
                if (lane == c*4+3) myword = w3;
            }
        }
        g_bits[(size_t)grow*32 + lane] = myword;
    } else if (blockIdx.x < PACK_BLOCKS + REC_BLOCKS) {
        __shared__ float sF[8][DD];
        int t = (blockIdx.x - PACK_BLOCKS) * blockDim.x + threadIdx.x;  // node
        float f[DD];
        #pragma unroll
        for (int d = 0; d < DD; d++) f[d] = feats[t*DD + d];
        float q[DD], k[DD], v[DD];
        #pragma unroll
        for (int e = 0; e < DD; e++) {
            float qq = 0.f, kk = 0.f, vv = 0.f;
            #pragma unroll
            for (int d = 0; d < DD; d++) {
                qq = fmaf(f[d], __ldg(&Wq[d*DD + e]), qq);
                kk = fmaf(f[d], __ldg(&Wk[d*DD + e]), kk);
                vv = fmaf(f[d], __ldg(&Wv[d*DD + e]), vv);
            }
            q[e] = qq; k[e] = kk; v[e] = vv;
        }
        const float qs = 0.44721359549995793f * LOG2E;  // log2e/sqrt(5)
        half2 q01 = __floats2half2_rn(q[0]*qs, q[1]*qs);
        half2 q23 = __floats2half2_rn(q[2]*qs, q[3]*qs);
        half2 q45 = __floats2half2_rn(q[4]*qs, 0.f);
        uint4 qh;
        qh.x = *(unsigned*)&q01; qh.y = *(unsigned*)&q23;
        qh.z = *(unsigned*)&q45; qh.w = 0;
        g_qh[t] = qh;                                   // true index
        float c0 = coors[t*3+0], c1 = coors[t*3+1], c2 = coors[t*3+2];
        half2 p01 = __floats2half2_rn(k[0], k[1]);
        half2 p23 = __floats2half2_rn(k[2], k[3]);
        half2 p45 = __floats2half2_rn(k[4], v[0]);
        half2 p67 = __floats2half2_rn(v[1], v[2]);
        uint4 kv;
        kv.x = *(unsigned*)&p01; kv.y = *(unsigned*)&p23;
        kv.z = *(unsigned*)&p45; kv.w = *(unsigned*)&p67;
        half2 p89 = __floats2half2_rn(v[3], v[4]);
        float4 vc;
        vc.x = *(float*)&p89; vc.y = c0; vc.z = c1; vc.w = c2;
        // permuted store position within batch
        int i  = t & (NN-1);
        int jp = (i >> 2) + (i & 3) * 256;
        int tp = (t & ~(NN-1)) + jp;
        g_kv[tp] = kv;
        g_vc[tp] = vc;
        // ---- feats partial sum for this block (fixed order, deterministic) ----
        int lane = threadIdx.x & 31, warp = threadIdx.x >> 5;
        #pragma unroll
        for (int off = 16; off; off >>= 1)
            #pragma unroll
            for (int d = 0; d < DD; d++)
                f[d] += __shfl_xor_sync(FULL, f[d], off);
        if (lane == 0)
            #pragma unroll
            for (int d = 0; d < DD; d++) sF[warp][d] = f[d];
        __syncthreads();
        if (threadIdx.x < DD) {
            float s = 0.f;
            #pragma unroll
            for (int w = 0; w < 8; w++) s += sF[w][threadIdx.x];
            g_fpart[(blockIdx.x - PACK_BLOCKS)*DD + threadIdx.x] = s;
        }
    } else if (threadIdx.x == 0) {
        // radial-MLP structure: with b1 == 0 (and dist > 0 always),
        // rbias(d) = d * sum_{h: w1_h>0} w1_h*w2_h + b2  -> single FMA.
        int simple = 1; float C = 0.f;
        #pragma unroll
        for (int h = 0; h < RH; h++) {
            float w1 = wr1[h];
            if (br1[h] != 0.f) simple = 0;
            if (w1 > 0.f) C = fmaf(w1, wr2[h], C);
        }
        g_simple = simple;
        g_C = C * LOG2E;
        g_bcShift = (br2[0] - 30.0f) * LOG2E;  // fixed softmax shift (scores bounded)
    }
}

__device__ __forceinline__ float ex2f(float x) {
    float y; asm("ex2.approx.f32 %0, %1;" : "=f"(y) : "f"(x)); return y;
}
__device__ __forceinline__ float sqrtapx(float x) {
    float y; asm("sqrt.approx.f32 %0, %1;" : "=f"(y) : "f"(x)); return y;
}

// warp-compact set bits of `acc` (lane owns word `lane`, permuted bit layout)
// into out[]; returns count.
// emitPerm=false: emit TRUE element  e  = (lane>>2)*128 + (lane&3) + 4*bit
// emitPerm=true : emit PERMUTED pos  jp = (lane>>2)*32 + (lane&3)*256 + bit
//                 (jp & 7 == bit & 7 -> consecutive bits cycle bank groups)
template<bool emitPerm>
__device__ __forceinline__ int warp_compact(unsigned acc, int lane,
                                            unsigned short* out) {
    const unsigned FULL = 0xffffffffu;
    int ebase = emitPerm ? (((lane >> 2) << 5) | ((lane & 3) << 8))
                         : (((lane >> 2) << 7) | (lane & 3));
    int c = __popc(acc);
    int pre = c;
    #pragma unroll
    for (int off = 1; off < 32; off <<= 1) {
        int vsh = __shfl_up_sync(FULL, pre, off);
        if (lane >= off) pre += vsh;
    }
    int total = __shfl_sync(FULL, pre, 31);
    int pos = pre - c;
    while (acc) {
        int bit = __ffs(acc) - 1; acc &= acc - 1;
        out[pos++] = (unsigned short)(ebase + (emitPerm ? bit : (bit << 2)));
    }
    return total;
}

// ------ fused 2-hop neighborhood + sparse attention + CTA pooling -----------
// 32 CTAs per batch, 256 threads (8 warps), 4 rows per warp.
// 2-hop build: compact 1-hop bits -> smem list (true indices, for bitset row
// addressing), OR neighbor rows (independent coalesced LDGs, x4), compact
// 2-hop bits emitting PERMUTED table positions, then gather (conflict-free
// bank-group cycling) with half2 score path and shifted no-max softmax.
__global__ void __launch_bounds__(256, 4)
k_attn(const float* __restrict__ wr1,
       const float* __restrict__ br1,
       const float* __restrict__ wr2) {
    extern __shared__ float smemf[];
    uint4*  sKV = (uint4*)smemf;                       // 16KB (permuted order)
    float4* sVC = (float4*)(sKV + NN);                 // 16KB (permuted order)
    unsigned short* sIdx = (unsigned short*)(sVC + NN);// 16KB
    float* sAgg = (float*)(sIdx + 8*NN);               // 32*5 = 640B
    int b   = blockIdx.x >> 5;
    int seg = blockIdx.x & 31;

    {
        const uint4*  t0 = g_kv + b*NN;
        const float4* t1 = g_vc + b*NN;
        for (int i = threadIdx.x; i < NN; i += 256) {
            sKV[i] = t0[i]; sVC[i] = t1[i];
        }
    }
    __syncthreads();

    int lane = threadIdx.x & 31, warp = threadIdx.x >> 5;
    unsigned short* widx = sIdx + warp * NN;
    const int   simple = g_simple;
    const float Cc     = g_C;
    const float bcS    = g_bcShift;
    const unsigned FULL = 0xffffffffu;

    #pragma unroll 1
    for (int r = 0; r < 4; r++) {
        int i   = seg * 32 + warp * 4 + r;    // row within batch
        int row = b * NN + i;

        // ---- stage 1: compact 1-hop bits into smem list (true indices) ----
        const unsigned* bb = g_bits + (size_t)(b*NN)*NWORDS;
        unsigned self = bb[(size_t)i*NWORDS + lane];
        int cnt1 = warp_compact<false>(self, lane, widx);
        __syncwarp(FULL);

        // ---- stage 2: OR 2-hop rows (independent coalesced LDGs) ----
        unsigned acc = self;
        {   // eye bit in permuted bit layout
            int wi = (((i >> 7) << 2) | (i & 3));
            if (lane == wi) acc |= 1u << ((i >> 2) & 31);
        }
        int p = 0;
        #pragma unroll 1
        for (; p + 4 <= cnt1; p += 4) {
            int j0 = (int)widx[p+0], j1 = (int)widx[p+1];
            int j2 = (int)widx[p+2], j3 = (int)widx[p+3];
            unsigned w0 = bb[(size_t)j0*NWORDS + lane];
            unsigned w1 = bb[(size_t)j1*NWORDS + lane];
            unsigned w2 = bb[(size_t)j2*NWORDS + lane];
            unsigned w3 = bb[(size_t)j3*NWORDS + lane];
            acc |= (w0 | w1) | (w2 | w3);
        }
        #pragma unroll 1
        for (; p < cnt1; p++)
            acc |= bb[(size_t)((int)widx[p])*NWORDS + lane];
        __syncwarp(FULL);

        // ---- stage 3: compact 2-hop bits (permuted table positions) ----
        int cnt = warp_compact<true>(acc, lane, widx);
        __syncwarp(FULL);

        // ---- gather + softmax-weighted aggregate ----
        uint4 qh = g_qh[row];
        half2 q01h = *(half2*)&qh.x;
        half2 q23h = *(half2*)&qh.y;
        half2 q45h = *(half2*)&qh.z;
        float4 ci = sVC[(i >> 2) + (i & 3) * 256];   // self at permuted pos
        float cx = ci.y, cy = ci.z, cz = ci.w;

        float s = 0.f;
        float a0 = 0.f, a1 = 0.f, a2 = 0.f, a3 = 0.f, a4 = 0.f;

        #pragma unroll 1
        for (int base = 0; base < cnt; base += 32) {
            int pp = base + lane;
            if (pp < cnt) {
                int j = (int)widx[pp];
                uint4  kv = sKV[j];
                float4 vc = sVC[j];
                // half2 score: (q0k0+q2k2+q4k4, q1k1+q3k3+0)
                half2 acc2 = __hmul2(q01h, *(half2*)&kv.x);
                acc2 = __hfma2(q23h, *(half2*)&kv.y, acc2);
                acc2 = __hfma2(q45h, *(half2*)&kv.z, acc2);
                float sc = bcS + __low2float(acc2) + __high2float(acc2);
                float dx = cx - vc.y, dy = cy - vc.z, dz = cz - vc.w;
                float d2 = fmaf(dx,dx, fmaf(dy,dy, fmaf(dz,dz, 1e-8f)));
                float dist = sqrtapx(d2);
                if (simple) {
                    sc = fmaf(dist, Cc, sc);
                } else {
                    float rb = 0.f;
                    #pragma unroll
                    for (int h = 0; h < RH; h++) {
                        float t = fmaf(dist, __ldg(&wr1[h]), __ldg(&br1[h]));
                        rb = fmaf(fmaxf(t, 0.f), __ldg(&wr2[h]), rb);
                    }
                    sc = fmaf(rb, LOG2E, sc);
                }
                float e = ex2f(sc);
                s += e;
                float  v0  = __high2float(*(half2*)&kv.z);
                float2 v12 = __half22float2(*(half2*)&kv.w);
                float2 v34 = __half22float2(*(half2*)&vc.x);
                a0 = fmaf(e, v0,    a0);
                a1 = fmaf(e, v12.x, a1);
                a2 = fmaf(e, v12.y, a2);
                a3 = fmaf(e, v34.x, a3);
                a4 = fmaf(e, v34.y, a4);
            }
        }
        // plain-sum warp merge (common shift cancels in normalization)
        #pragma unroll
        for (int off = 16; off; off >>= 1) {
            s  += __shfl_xor_sync(FULL, s,  off);
            a0 += __shfl_xor_sync(FULL, a0, off);
            a1 += __shfl_xor_sync(FULL, a1, off);
            a2 += __shfl_xor_sync(FULL, a2, off);
            a3 += __shfl_xor_sync(FULL, a3, off);
            a4 += __shfl_xor_sync(FULL, a4, off);
        }
        if (lane == 0) {
            float inv = 1.f / s;
            float* dst = sAgg + (warp*4 + r)*DD;
            dst[0] = a0*inv; dst[1] = a1*inv; dst[2] = a2*inv;
            dst[3] = a3*inv; dst[4] = a4*inv;
        }
        __syncwarp(FULL);
    }
    __syncthreads();
    if (threadIdx.x < DD) {
        float t = 0.f;
        #pragma unroll 1
        for (int rr = 0; rr < 32; rr++) t += sAgg[rr*DD + threadIdx.x];
        g_part[blockIdx.x*DD + threadIdx.x] = t;   // fixed order -> deterministic
    }
}

// ------- head: combine agg partials + feats partials, Wo, MLP (tiny) --------
__global__ void k_head(const float* __restrict__ Wo,
                       const float* __restrict__ w1, const float* __restrict__ b1,
                       const float* __restrict__ w2, const float* __restrict__ b2,
                       float* __restrict__ out) {
    int b = blockIdx.x;
    int t = threadIdx.x;              // 256 threads
    __shared__ float spA[DD], sp[DD];
    __shared__ float sh[128];

    if (t < DD) {
        float sa = 0.f;
        #pragma unroll 1
        for (int sg = 0; sg < 32; sg++) sa += g_part[(b*32 + sg)*DD + t];
        spA[t] = sa * (1.0f/NN);
        float sf = 0.f;
        #pragma unroll
        for (int k = 0; k < 4; k++) sf += g_fpart[(b*4 + k)*DD + t];
        sp[t] = sf * (1.0f/NN);       // feats mean; Wo term added below
    }
    __syncthreads();
    if (t < DD) {
        float o = sp[t];
        #pragma unroll
        for (int d = 0; d < DD; d++) o = fmaf(spA[d], __ldg(&Wo[d*DD + t]), o);
        sp[t] = o;
    }
    __syncthreads();
    if (t < 128) {
        float h = b1[t];
        #pragma unroll
        for (int d = 0; d < DD; d++) h = fmaf(sp[d], w1[d*128 + t], h);
        sh[t] = fmaxf(h, 0.f);
    }
    __syncthreads();
    if (t < 3) {
        float o = b2[t];
        for (int h = 0; h < 128; h++) o = fmaf(sh[h], w2[h*3 + t], o);
        out[b*3 + t] = o;
    }
}

// ---------------- launcher ---------------------------------------------------
extern "C" void kernel_launch(void* const* d_in, const int* in_sizes, int n_in,
                              void* d_out, int out_size) {
    const float* feats = (const float*)d_in[0];
    const float* coors = (const float*)d_in[1];
    const void*  adj   = d_in[2];
    const float* Wq    = (const float*)d_in[3];
    const float* Wk    = (const float*)d_in[4];
    const float* Wv    = (const float*)d_in[5];
    const float* Wo    = (const float*)d_in[6];
    const float* wr1   = (const float*)d_in[7];
    const float* br1   = (const float*)d_in[8];
    const float* wr2   = (const float*)d_in[9];
    const float* br2   = (const float*)d_in[10];
    const float* w1    = (const float*)d_in[11];
    const float* b1    = (const float*)d_in[12];
    const float* w2    = (const float*)d_in[13];
    const float* b2    = (const float*)d_in[14];
    float* out = (float*)d_out;

    const int ATTN_SMEM = 48*1024 + 32*DD*4;   // tables + idx + agg
    cudaFuncSetAttribute(k_attn, cudaFuncAttributeMaxDynamicSharedMemorySize, ATTN_SMEM);

    k_pack_rec<<<PACK_BLOCKS + REC_BLOCKS + 1, 256>>>((const unsigned*)adj, feats, coors,
                                                      Wq, Wk, Wv, wr1, br1, wr2, br2);
    k_attn<<<BB*32, 256, ATTN_SMEM>>>(wr1, br1, wr2);
    k_head<<<BB, 256>>>(Wo, w1, b1, w2, b2, out);
}

// round 15
// speedup vs baseline: 1.0907x; 1.0907x over previous
#include <cuda_runtime.h>
#include <cuda_fp16.h>
#include <math.h>
#include <float.h>

#define BB 16
#define NN 1024
#define DD 5
#define RH 8
#define NWORDS 32            // 1024 bits / 32
#define ROWS (BB*NN)         // 16384
#define PACK_BLOCKS (ROWS/8)              // 2048 (8 warps/blk, 1 row/warp)
#define REC_BLOCKS  (ROWS/256)            // 64
#define LOG2E 1.4426950408889634f

// ---------------- scratch (static device globals; no runtime alloc) --------
// g_bits uses a PERMUTED bit layout (pack<->attn private):
//   row element e: chunk c=e>>7, lane=(e>>2)&31, k=e&3; word w'=c*4+k, bit=lane
//   decode: e = (w'>>2)*128 + bit*4 + (w'&3)
// g_kv/g_vc are stored at PERMUTED within-batch position
//   jp(i) = (i>>2) + (i&3)*256   (bijection on 0..1023)
// so that compacted gather indices cycle all 8 smem 16B bank-groups.
__device__ unsigned int g_bits[ROWS*NWORDS];   // packed 1-hop adjacency (2 MB)
__device__ uint4        g_kv[ROWS];            // fp16: (k0,k1)(k2,k3)(k4,v0)(v1,v2)
__device__ float4       g_vc[ROWS];            // .x = half2(v3,v4), .y..w = coors
__device__ uint4        g_qh[ROWS];            // half2: q01,q23,(q4,0); pre-scaled
__device__ float        g_part[BB*32*DD];      // per-CTA agg partial sums
__device__ int          g_simple;              // rbias is linear in dist
__device__ float        g_C, g_bcShift;        // log2e-scaled slope / shifted bias

// ------- pack adjacency bitset + build node tables + radial coeffs ---------
// dtype probe (per pack block, same first 8KB -> L2-resident):
//   uint8 bools: nonzero at all byte offsets       -> fa=1, fb=1
//   int32 bools: nonzero only at offset%4==0       -> fa=1, fb=0
//   f32   bools: 1.0f bytes at offsets 2,3         -> fa=0, fb=1
// Pack: lane loads uint4/uchar4 (4 consecutive elements), 4 ballots per
// 128-element chunk form words in the permuted layout; coalesced store.
// (Kept minimal: extra work fused into any branch raises the WHOLE kernel's
// reg/smem footprint and tanks pack occupancy -- R14 lesson.)
__global__ void k_pack_rec(const unsigned* __restrict__ a,
                           const float* __restrict__ feats,
                           const float* __restrict__ coors,
                           const float* __restrict__ Wq,
                           const float* __restrict__ Wk,
                           const float* __restrict__ Wv,
                           const float* __restrict__ wr1,
                           const float* __restrict__ br1,
                           const float* __restrict__ wr2,
                           const float* __restrict__ br2) {
    const unsigned FULL = 0xffffffffu;
    if (blockIdx.x < PACK_BLOCKS) {
        __shared__ unsigned sFa, sFb;
        if (threadIdx.x == 0) { sFa = 0; sFb = 0; }
        __syncthreads();
        {
            const uchar4* p8 = (const uchar4*)a;
            unsigned fa = 0, fb = 0;
            #pragma unroll
            for (int k = 0; k < 8; k++) {
                uchar4 u = p8[threadIdx.x + k*256];
                fa |= u.x;
                fb |= (unsigned)(u.y | u.z | u.w);
            }
            if (fa) atomicOr(&sFa, 1u);
            if (fb) atomicOr(&sFb, 1u);
        }
        __syncthreads();
        bool u8 = sFa && sFb;

        int lane = threadIdx.x & 31;
        int grow = blockIdx.x * 8 + (threadIdx.x >> 5);   // row 0..16383
        unsigned myword = 0;
        if (u8) {
            const uchar4* a4 = (const uchar4*)a;
            #pragma unroll
            for (int c = 0; c < 8; c++) {
                uchar4 u = a4[(size_t)grow*256 + c*32 + lane];
                unsigned w0 = __ballot_sync(FULL, u.x != 0);
                unsigned w1 = __ballot_sync(FULL, u.y != 0);
                unsigned w2 = __ballot_sync(FULL, u.z != 0);
                unsigned w3 = __ballot_sync(FULL, u.w != 0);
                if (lane == c*4+0) myword = w0;
                if (lane == c*4+1) myword = w1;
                if (lane == c*4+2) myword = w2;
                if (lane == c*4+3) myword = w3;
            }
        } else {
            const uint4* a4 = (const uint4*)a;
            #pragma unroll
            for (int c = 0; c < 8; c++) {
                uint4 u = a4[(size_t)grow*256 + c*32 + lane];
                unsigned w0 = __ballot_sync(FULL, u.x != 0);
                unsigned w1 = __ballot_sync(FULL, u.y != 0);
                unsigned w2 = __ballot_sync(FULL, u.z != 0);
                unsigned w3 = __ballot_sync(FULL, u.w != 0);
                if (lane == c*4+0) myword = w0;
                if (lane == c*4+1) myword = w1;
                if (lane == c*4+2) myword = w2;
                if (lane == c*4+3) myword = w3;
            }
        }
        g_bits[(size_t)grow*32 + lane] = myword;
    } else if (blockIdx.x < PACK_BLOCKS + REC_BLOCKS) {
        int t = (blockIdx.x - PACK_BLOCKS) * blockDim.x + threadIdx.x;  // node
        float f[DD];
        #pragma unroll
        for (int d = 0; d < DD; d++) f[d] = feats[t*DD + d];
        float q[DD], k[DD], v[DD];
        #pragma unroll
        for (int e = 0; e < DD; e++) {
            float qq = 0.f, kk = 0.f, vv = 0.f;
            #pragma unroll
            for (int d = 0; d < DD; d++) {
                qq = fmaf(f[d], __ldg(&Wq[d*DD + e]), qq);
                kk = fmaf(f[d], __ldg(&Wk[d*DD + e]), kk);
                vv = fmaf(f[d], __ldg(&Wv[d*DD + e]), vv);
            }
            q[e] = qq; k[e] = kk; v[e] = vv;
        }
        const float qs = 0.44721359549995793f * LOG2E;  // log2e/sqrt(5)
        half2 q01 = __floats2half2_rn(q[0]*qs, q[1]*qs);
        half2 q23 = __floats2half2_rn(q[2]*qs, q[3]*qs);
        half2 q45 = __floats2half2_rn(q[4]*qs, 0.f);
        uint4 qh;
        qh.x = *(unsigned*)&q01; qh.y = *(unsigned*)&q23;
        qh.z = *(unsigned*)&q45; qh.w = 0;
        g_qh[t] = qh;                                   // true index
        float c0 = coors[t*3+0], c1 = coors[t*3+1], c2 = coors[t*3+2];
        half2 p01 = __floats2half2_rn(k[0], k[1]);
        half2 p23 = __floats2half2_rn(k[2], k[3]);
        half2 p45 = __floats2half2_rn(k[4], v[0]);
        half2 p67 = __floats2half2_rn(v[1], v[2]);
        uint4 kv;
        kv.x = *(unsigned*)&p01; kv.y = *(unsigned*)&p23;
        kv.z = *(unsigned*)&p45; kv.w = *(unsigned*)&p67;
        half2 p89 = __floats2half2_rn(v[3], v[4]);
        float4 vc;
        vc.x = *(float*)&p89; vc.y = c0; vc.z = c1; vc.w = c2;
        // permuted store position within batch
        int i  = t & (NN-1);
        int jp = (i >> 2) + (i & 3) * 256;
        int tp = (t & ~(NN-1)) + jp;
        g_kv[tp] = kv;
        g_vc[tp] = vc;
    } else if (threadIdx.x == 0) {
        // radial-MLP structure: with b1 == 0 (and dist > 0 always),
        // rbias(d) = d * sum_{h: w1_h>0} w1_h*w2_h + b2  -> single FMA.
        int simple = 1; float C = 0.f;
        #pragma unroll
        for (int h = 0; h < RH; h++) {
            float w1 = wr1[h];
            if (br1[h] != 0.f) simple = 0;
            if (w1 > 0.f) C = fmaf(w1, wr2[h], C);
        }
        g_simple = simple;
        g_C = C * LOG2E;
        g_bcShift = (br2[0] - 30.0f) * LOG2E;  // fixed softmax shift (scores bounded)
    }
}

__device__ __forceinline__ float ex2f(float x) {
    float y; asm("ex2.approx.f32 %0, %1;" : "=f"(y) : "f"(x)); return y;
}
__device__ __forceinline__ float sqrtapx(float x) {
    float y; asm("sqrt.approx.f32 %0, %1;" : "=f"(y) : "f"(x)); return y;
}

// warp-compact set bits of `acc` (lane owns word `lane`, permuted bit layout)
// into out[]; returns count.
// emitPerm=false: emit TRUE element  e  = (lane>>2)*128 + (lane&3) + 4*bit
// emitPerm=true : emit PERMUTED pos  jp = (lane>>2)*32 + (lane&3)*256 + bit
//                 (jp & 7 == bit & 7 -> consecutive bits cycle bank groups)
template<bool emitPerm>
__device__ __forceinline__ int warp_compact(unsigned acc, int lane,
                                            unsigned short* out) {
    const unsigned FULL = 0xffffffffu;
    int ebase = emitPerm ? (((lane >> 2) << 5) | ((lane & 3) << 8))
                         : (((lane >> 2) << 7) | (lane & 3));
    int c = __popc(acc);
    int pre = c;
    #pragma unroll
    for (int off = 1; off < 32; off <<= 1) {
        int vsh = __shfl_up_sync(FULL, pre, off);
        if (lane >= off) pre += vsh;
    }
    int total = __shfl_sync(FULL, pre, 31);
    int pos = pre - c;
    while (acc) {
        int bit = __ffs(acc) - 1; acc &= acc - 1;
        out[pos++] = (unsigned short)(ebase + (emitPerm ? bit : (bit << 2)));
    }
    return total;
}

// ------ fused 2-hop neighborhood + sparse attention + CTA pooling -----------
// 32 CTAs per batch, 256 threads (8 warps), 4 rows per warp.
// 2-hop build: compact 1-hop bits -> smem list (true indices, for bitset row
// addressing), OR neighbor rows (independent coalesced LDGs, x4), compact
// 2-hop bits emitting PERMUTED table positions, then gather (conflict-free
// bank-group cycling) with half2 score path and shifted no-max softmax.
__global__ void __launch_bounds__(256, 4)
k_attn(const float* __restrict__ wr1,
       const float* __restrict__ br1,
       const float* __restrict__ wr2) {
    extern __shared__ float smemf[];
    uint4*  sKV = (uint4*)smemf;                       // 16KB (permuted order)
    float4* sVC = (float4*)(sKV + NN);                 // 16KB (permuted order)
    unsigned short* sIdx = (unsigned short*)(sVC + NN);// 16KB
    float* sAgg = (float*)(sIdx + 8*NN);               // 32*5 = 640B
    int b   = blockIdx.x >> 5;
    int seg = blockIdx.x & 31;

    {
        const uint4*  t0 = g_kv + b*NN;
        const float4* t1 = g_vc + b*NN;
        for (int i = threadIdx.x; i < NN; i += 256) {
            sKV[i] = t0[i]; sVC[i] = t1[i];
        }
    }
    __syncthreads();

    int lane = threadIdx.x & 31, warp = threadIdx.x >> 5;
    unsigned short* widx = sIdx + warp * NN;
    const int   simple = g_simple;
    const float Cc     = g_C;
    const float bcS    = g_bcShift;
    const unsigned FULL = 0xffffffffu;

    #pragma unroll 1
    for (int r = 0; r < 4; r++) {
        int i   = seg * 32 + warp * 4 + r;    // row within batch
        int row = b * NN + i;

        // ---- stage 1: compact 1-hop bits into smem list (true indices) ----
        const unsigned* bb = g_bits + (size_t)(b*NN)*NWORDS;
        unsigned self = bb[(size_t)i*NWORDS + lane];
        int cnt1 = warp_compact<false>(self, lane, widx);
        __syncwarp(FULL);

        // ---- stage 2: OR 2-hop rows (independent coalesced LDGs) ----
        unsigned acc = self;
        {   // eye bit in permuted bit layout
            int wi = (((i >> 7) << 2) | (i & 3));
            if (lane == wi) acc |= 1u << ((i >> 2) & 31);
        }
        int p = 0;
        #pragma unroll 1
        for (; p + 4 <= cnt1; p += 4) {
            int j0 = (int)widx[p+0], j1 = (int)widx[p+1];
            int j2 = (int)widx[p+2], j3 = (int)widx[p+3];
            unsigned w0 = bb[(size_t)j0*NWORDS + lane];
            unsigned w1 = bb[(size_t)j1*NWORDS + lane];
            unsigned w2 = bb[(size_t)j2*NWORDS + lane];
            unsigned w3 = bb[(size_t)j3*NWORDS + lane];
            acc |= (w0 | w1) | (w2 | w3);
        }
        #pragma unroll 1
        for (; p < cnt1; p++)
            acc |= bb[(size_t)((int)widx[p])*NWORDS + lane];
        __syncwarp(FULL);

        // ---- stage 3: compact 2-hop bits (permuted table positions) ----
        int cnt = warp_compact<true>(acc, lane, widx);
        __syncwarp(FULL);

        // ---- gather + softmax-weighted aggregate ----
        uint4 qh = g_qh[row];
        half2 q01h = *(half2*)&qh.x;
        half2 q23h = *(half2*)&qh.y;
        half2 q45h = *(half2*)&qh.z;
        float4 ci = sVC[(i >> 2) + (i & 3) * 256];   // self at permuted pos
        float cx = ci.y, cy = ci.z, cz = ci.w;

        float s = 0.f;
        float a0 = 0.f, a1 = 0.f, a2 = 0.f, a3 = 0.f, a4 = 0.f;

        #pragma unroll 1
        for (int base = 0; base < cnt; base += 32) {
            int pp = base + lane;
            if (pp < cnt) {
                int j = (int)widx[pp];
                uint4  kv = sKV[j];
                float4 vc = sVC[j];
                // half2 score: (q0k0+q2k2+q4k4, q1k1+q3k3+0)
                half2 acc2 = __hmul2(q01h, *(half2*)&kv.x);
                acc2 = __hfma2(q23h, *(half2*)&kv.y, acc2);
                acc2 = __hfma2(q45h, *(half2*)&kv.z, acc2);
                float sc = bcS + __low2float(acc2) + __high2float(acc2);
                float dx = cx - vc.y, dy = cy - vc.z, dz = cz - vc.w;
                float d2 = fmaf(dx,dx, fmaf(dy,dy, fmaf(dz,dz, 1e-8f)));
                float dist = sqrtapx(d2);
                if (simple) {
                    sc = fmaf(dist, Cc, sc);
                } else {
                    float rb = 0.f;
                    #pragma unroll
                    for (int h = 0; h < RH; h++) {
                        float t = fmaf(dist, __ldg(&wr1[h]), __ldg(&br1[h]));
                        rb = fmaf(fmaxf(t, 0.f), __ldg(&wr2[h]), rb);
                    }
                    sc = fmaf(rb, LOG2E, sc);
                }
                float e = ex2f(sc);
                s += e;
                float  v0  = __high2float(*(half2*)&kv.z);
                float2 v12 = __half22float2(*(half2*)&kv.w);
                float2 v34 = __half22float2(*(half2*)&vc.x);
                a0 = fmaf(e, v0,    a0);
                a1 = fmaf(e, v12.x, a1);
                a2 = fmaf(e, v12.y, a2);
                a3 = fmaf(e, v34.x, a3);
                a4 = fmaf(e, v34.y, a4);
            }
        }
        // plain-sum warp merge (common shift cancels in normalization)
        #pragma unroll
        for (int off = 16; off; off >>= 1) {
            s  += __shfl_xor_sync(FULL, s,  off);
            a0 += __shfl_xor_sync(FULL, a0, off);
            a1 += __shfl_xor_sync(FULL, a1, off);
            a2 += __shfl_xor_sync(FULL, a2, off);
            a3 += __shfl_xor_sync(FULL, a3, off);
            a4 += __shfl_xor_sync(FULL, a4, off);
        }
        if (lane == 0) {
            float inv = 1.f / s;
            float* dst = sAgg + (warp*4 + r)*DD;
            dst[0] = a0*inv; dst[1] = a1*inv; dst[2] = a2*inv;
            dst[3] = a3*inv; dst[4] = a4*inv;
        }
        __syncwarp(FULL);
    }
    __syncthreads();
    if (threadIdx.x < DD) {
        float t = 0.f;
        #pragma unroll 1
        for (int rr = 0; rr < 32; rr++) t += sAgg[rr*DD + threadIdx.x];
        g_part[blockIdx.x*DD + threadIdx.x] = t;   // fixed order -> deterministic
    }
}

// ---------------- head: pool feats + agg partials, Wo, MLP ------------------
// feats pooling vectorized: 4 nodes = 20 floats = exactly 5 float4s, so
// thread t loads floats [20t, 20t+20) with 5 LDG.128 (one pass, 256 threads
// cover all 1024 nodes) and sums components into the 5 buckets with static
// mapping -- 4x fewer LSU ops than the scalar form.
__global__ void k_head(const float* __restrict__ feats,
                       const float* __restrict__ Wo,
                       const float* __restrict__ w1, const float* __restrict__ b1,
                       const float* __restrict__ w2, const float* __restrict__ b2,
                       float* __restrict__ out) {
    int b = blockIdx.x;
    int t = threadIdx.x;              // 256 threads
    int lane = t & 31, warp = t >> 5;
    __shared__ float wsF[8][DD];
    __shared__ float spF[DD], spA[DD], sp[DD];
    __shared__ float sh[128];

    float lf[DD];
    {
        const float4* f4 = (const float4*)(feats + (size_t)b*NN*DD);
        float4 u0 = f4[t*5+0], u1 = f4[t*5+1], u2 = f4[t*5+2];
        float4 u3 = f4[t*5+3], u4 = f4[t*5+4];
        // nodes: {u0.x..u1.x} {u1.y..u2.y} {u2.z..u3.z} {u3.w..u4.w}
        lf[0] = (u0.x + u1.y) + (u2.z + u3.w);
        lf[1] = (u0.y + u1.z) + (u2.w + u4.x);
        lf[2] = (u0.z + u1.w) + (u3.x + u4.y);
        lf[3] = (u0.w + u2.x) + (u3.y + u4.z);
        lf[4] = (u1.x + u2.y) + (u3.z + u4.w);
    }
    float la[DD] = {0.f,0.f,0.f,0.f,0.f};
    if (t < 32) {
        const float* p = g_part + (b*32 + t)*DD;
        #pragma unroll
        for (int d = 0; d < DD; d++) la[d] = p[d];
    }
    #pragma unroll
    for (int off = 16; off; off >>= 1) {
        #pragma unroll
        for (int d = 0; d < DD; d++) {
            lf[d] += __shfl_xor_sync(0xffffffffu, lf[d], off);
            la[d] += __shfl_xor_sync(0xffffffffu, la[d], off);
        }
    }
    if (lane == 0) {
        #pragma unroll
        for (int d = 0; d < DD; d++) wsF[warp][d] = lf[d];
        if (warp == 0) {
            #pragma unroll
            for (int d = 0; d < DD; d++) spA[d] = la[d] * (1.0f/NN);
        }
    }
    __syncthreads();
    if (t < DD) {
        float s = 0.f;
        #pragma unroll
        for (int w = 0; w < 8; w++) s += wsF[w][t];
        spF[t] = s * (1.0f/NN);
    }
    __syncthreads();
    if (t < DD) {
        float o = spF[t];
        #pragma unroll
        for (int d = 0; d < DD; d++) o = fmaf(spA[d], __ldg(&Wo[d*DD + t]), o);
        sp[t] = o;
    }
    __syncthreads();
    if (t < 128) {
        float h = b1[t];
        #pragma unroll
        for (int d = 0; d < DD; d++) h = fmaf(sp[d], w1[d*128 + t], h);
        sh[t] = fmaxf(h, 0.f);
    }
    __syncthreads();
    if (t < 3) {
        float o = b2[t];
        for (int h = 0; h < 128; h++) o = fmaf(sh[h], w2[h*3 + t], o);
        out[b*3 + t] = o;
    }
}

// ---------------- launcher ---------------------------------------------------
extern "C" void kernel_launch(void* const* d_in, const int* in_sizes, int n_in,
                              void* d_out, int out_size) {
    const float* feats = (const float*)d_in[0];
    const float* coors = (const float*)d_in[1];
    const void*  adj   = d_in[2];
    const float* Wq    = (const float*)d_in[3];
    const float* Wk    = (const float*)d_in[4];
    const float* Wv    = (const float*)d_in[5];
    const float* Wo    = (const float*)d_in[6];
    const float* wr1   = (const float*)d_in[7];
    const float* br1   = (const float*)d_in[8];
    const float* wr2   = (const float*)d_in[9];
    const float* br2   = (const float*)d_in[10];
    const float* w1    = (const float*)d_in[11];
    const float* b1    = (const float*)d_in[12];
    const float* w2    = (const float*)d_in[13];
    const float* b2    = (const float*)d_in[14];
    float* out = (float*)d_out;

    const int ATTN_SMEM = 48*1024 + 32*DD*4;   // tables + idx + agg
    cudaFuncSetAttribute(k_attn, cudaFuncAttributeMaxDynamicSharedMemorySize, ATTN_SMEM);

    k_pack_rec<<<PACK_BLOCKS + REC_BLOCKS + 1, 256>>>((const unsigned*)adj, feats, coors,
                                                      Wq, Wk, Wv, wr1, br1, wr2, br2);
    k_attn<<<BB*32, 256, ATTN_SMEM>>>(wr1, br1, wr2);
    k_head<<<BB, 256>>>(feats, Wo, w1, b1, w2, b2, out);
}

// round 16
// speedup vs baseline: 1.0915x; 1.0007x over previous
#include <cuda_runtime.h>
#include <cuda_fp16.h>
#include <math.h>
#include <float.h>

#define BB 16
#define NN 1024
#define DD 5
#define RH 8
#define NWORDS 32            // 1024 bits / 32
#define ROWS (BB*NN)         // 16384
#define PACK_BLOCKS (ROWS/8)              // 2048 (8 warps/blk, 1 row/warp)
#define REC_BLOCKS  (ROWS/256)            // 64
#define LOG2E 1.4426950408889634f

// ---------------- scratch (static device globals; no runtime alloc) --------
// g_bits uses a PERMUTED bit layout (pack<->attn private):
//   row element e: chunk c=e>>7, lane=(e>>2)&31, k=e&3; word w'=c*4+k, bit=lane
//   decode: e = (w'>>2)*128 + bit*4 + (w'&3)
// g_kv/g_vc are stored at PERMUTED within-batch position
//   jp(i) = (i>>2) + (i&3)*256   (bijection on 0..1023)
// so that compacted gather indices cycle all 8 smem 16B bank-groups.
__device__ unsigned int g_bits[ROWS*NWORDS];   // packed 1-hop adjacency (2 MB)
__device__ uint4        g_kv[ROWS];            // fp16: (k0,k1)(k2,k3)(k4,v0)(v1,v2)
__device__ float4       g_vc[ROWS];            // .x = half2(v3,v4), .y..w = coors
__device__ uint4        g_qh[ROWS];            // half2: q01,q23,(q4,0); pre-scaled
__device__ float        g_part[BB*32*DD];      // per-CTA agg partial sums
__device__ int          g_simple;              // rbias is linear in dist
__device__ float        g_C, g_bcShift;        // log2e-scaled slope / shifted bias

// ------- pack adjacency bitset + build node tables + radial coeffs ---------
// dtype probe (per pack block, first 8KB, VECTORIZED 2xLDG.128/thread --
// the old 8x scalar-load probe doubled the kernel's LSU ops):
//   uint8 bools: nonzero at all byte offsets       -> fa=1, fb=1
//   int32 bools: nonzero only at offset%4==0       -> fa=1, fb=0
//   f32   bools: 1.0f bytes at offsets 2,3         -> fa=0, fb=1
// Pack: lane loads uint4/uchar4 (4 consecutive elements), 4 ballots per
// 128-element chunk form words in the permuted layout; coalesced store.
__global__ void k_pack_rec(const unsigned* __restrict__ a,
                           const float* __restrict__ feats,
                           const float* __restrict__ coors,
                           const float* __restrict__ Wq,
                           const float* __restrict__ Wk,
                           const float* __restrict__ Wv,
                           const float* __restrict__ wr1,
                           const float* __restrict__ br1,
                           const float* __restrict__ wr2,
                           const float* __restrict__ br2) {
    const unsigned FULL = 0xffffffffu;
    if (blockIdx.x < PACK_BLOCKS) {
        __shared__ unsigned sFa, sFb;
        if (threadIdx.x == 0) { sFa = 0; sFb = 0; }
        __syncthreads();
        {
            const uint4* p16 = (const uint4*)a;
            unsigned fa = 0, fb = 0;
            #pragma unroll
            for (int k = 0; k < 2; k++) {
                uint4 u = p16[threadIdx.x + k*256];   // 16B; same 8KB window
                unsigned m0 = u.x | u.z, m1 = u.y | u.w;
                unsigned any = m0 | m1;
                fa |= (m0 | m1) & 0x000000FFu;        // byte offset 0 mod 4
                fb |= any & 0xFFFFFF00u;              // byte offsets 1..3
            }
            if (fa) atomicOr(&sFa, 1u);
            if (fb) atomicOr(&sFb, 1u);
        }
        __syncthreads();
        bool u8 = sFa && sFb;

        int lane = threadIdx.x & 31;
        int grow = blockIdx.x * 8 + (threadIdx.x >> 5);   // row 0..16383
        unsigned myword = 0;
        if (u8) {
            const uchar4* a4 = (const uchar4*)a;
            #pragma unroll
            for (int c = 0; c < 8; c++) {
                uchar4 u = a4[(size_t)grow*256 + c*32 + lane];
                unsigned w0 = __ballot_sync(FULL, u.x != 0);
                unsigned w1 = __ballot_sync(FULL, u.y != 0);
                unsigned w2 = __ballot_sync(FULL, u.z != 0);
                unsigned w3 = __ballot_sync(FULL, u.w != 0);
                if (lane == c*4+0) myword = w0;
                if (lane == c*4+1) myword = w1;
                if (lane == c*4+2) myword = w2;
                if (lane == c*4+3) myword = w3;
            }
        } else {
            const uint4* a4 = (const uint4*)a;
            #pragma unroll
            for (int c = 0; c < 8; c++) {
                uint4 u = a4[(size_t)grow*256 + c*32 + lane];
                unsigned w0 = __ballot_sync(FULL, u.x != 0);
                unsigned w1 = __ballot_sync(FULL, u.y != 0);
                unsigned w2 = __ballot_sync(FULL, u.z != 0);
                unsigned w3 = __ballot_sync(FULL, u.w != 0);
                if (lane == c*4+0) myword = w0;
                if (lane == c*4+1) myword = w1;
                if (lane == c*4+2) myword = w2;
                if (lane == c*4+3) myword = w3;
            }
        }
        g_bits[(size_t)grow*32 + lane] = myword;
    } else if (blockIdx.x < PACK_BLOCKS + REC_BLOCKS) {
        int t = (blockIdx.x - PACK_BLOCKS) * blockDim.x + threadIdx.x;  // node
        float f[DD];
        #pragma unroll
        for (int d = 0; d < DD; d++) f[d] = feats[t*DD + d];
        float q[DD], k[DD], v[DD];
        #pragma unroll
        for (int e = 0; e < DD; e++) {
            float qq = 0.f, kk = 0.f, vv = 0.f;
            #pragma unroll
            for (int d = 0; d < DD; d++) {
                qq = fmaf(f[d], __ldg(&Wq[d*DD + e]), qq);
                kk = fmaf(f[d], __ldg(&Wk[d*DD + e]), kk);
                vv = fmaf(f[d], __ldg(&Wv[d*DD + e]), vv);
            }
            q[e] = qq; k[e] = kk; v[e] = vv;
        }
        const float qs = 0.44721359549995793f * LOG2E;  // log2e/sqrt(5)
        half2 q01 = __floats2half2_rn(q[0]*qs, q[1]*qs);
        half2 q23 = __floats2half2_rn(q[2]*qs, q[3]*qs);
        half2 q45 = __floats2half2_rn(q[4]*qs, 0.f);
        uint4 qh;
        qh.x = *(unsigned*)&q01; qh.y = *(unsigned*)&q23;
        qh.z = *(unsigned*)&q45; qh.w = 0;
        g_qh[t] = qh;                                   // true index
        float c0 = coors[t*3+0], c1 = coors[t*3+1], c2 = coors[t*3+2];
        half2 p01 = __floats2half2_rn(k[0], k[1]);
        half2 p23 = __floats2half2_rn(k[2], k[3]);
        half2 p45 = __floats2half2_rn(k[4], v[0]);
        half2 p67 = __floats2half2_rn(v[1], v[2]);
        uint4 kv;
        kv.x = *(unsigned*)&p01; kv.y = *(unsigned*)&p23;
        kv.z = *(unsigned*)&p45; kv.w = *(unsigned*)&p67;
        half2 p89 = __floats2half2_rn(v[3], v[4]);
        float4 vc;
        vc.x = *(float*)&p89; vc.y = c0; vc.z = c1; vc.w = c2;
        // permuted store position within batch
        int i  = t & (NN-1);
        int jp = (i >> 2) + (i & 3) * 256;
        int tp = (t & ~(NN-1)) + jp;
        g_kv[tp] = kv;
        g_vc[tp] = vc;
    } else if (threadIdx.x == 0) {
        // radial-MLP structure: with b1 == 0 (and dist > 0 always),
        // rbias(d) = d * sum_{h: w1_h>0} w1_h*w2_h + b2  -> single FMA.
        int simple = 1; float C = 0.f;
        #pragma unroll
        for (int h = 0; h < RH; h++) {
            float w1 = wr1[h];
            if (br1[h] != 0.f) simple = 0;
            if (w1 > 0.f) C = fmaf(w1, wr2[h], C);
        }
        g_simple = simple;
        g_C = C * LOG2E;
        g_bcShift = (br2[0] - 30.0f) * LOG2E;  // fixed softmax shift (scores bounded)
    }
}

__device__ __forceinline__ float ex2f(float x) {
    float y; asm("ex2.approx.f32 %0, %1;" : "=f"(y) : "f"(x)); return y;
}
__device__ __forceinline__ float sqrtapx(float x) {
    float y; asm("sqrt.approx.f32 %0, %1;" : "=f"(y) : "f"(x)); return y;
}

// warp-compact set bits of `acc` (lane owns word `lane`, permuted bit layout)
// into out[]; returns count.
// emitPerm=false: emit TRUE element  e  = (lane>>2)*128 + (lane&3) + 4*bit
// emitPerm=true : emit PERMUTED pos  jp = (lane>>2)*32 + (lane&3)*256 + bit
//                 (jp & 7 == bit & 7 -> consecutive bits cycle bank groups)
template<bool emitPerm>
__device__ __forceinline__ int warp_compact(unsigned acc, int lane,
                                            unsigned short* out) {
    const unsigned FULL = 0xffffffffu;
    int ebase = emitPerm ? (((lane >> 2) << 5) | ((lane & 3) << 8))
                         : (((lane >> 2) << 7) | (lane & 3));
    int c = __popc(acc);
    int pre = c;
    #pragma unroll
    for (int off = 1; off < 32; off <<= 1) {
        int vsh = __shfl_up_sync(FULL, pre, off);
        if (lane >= off) pre += vsh;
    }
    int total = __shfl_sync(FULL, pre, 31);
    int pos = pre - c;
    while (acc) {
        int bit = __ffs(acc) - 1; acc &= acc - 1;
        out[pos++] = (unsigned short)(ebase + (emitPerm ? bit : (bit << 2)));
    }
    return total;
}

// ------ fused 2-hop neighborhood + sparse attention + CTA pooling -----------
// 32 CTAs per batch, 256 threads (8 warps), 4 rows per warp.
// 2-hop build: compact 1-hop bits -> smem list (true indices, for bitset row
// addressing), OR neighbor rows (independent coalesced LDGs, x4), compact
// 2-hop bits emitting PERMUTED table positions, then gather (conflict-free
// bank-group cycling) with half2 score path and shifted no-max softmax.
__global__ void __launch_bounds__(256, 4)
k_attn(const float* __restrict__ wr1,
       const float* __restrict__ br1,
       const float* __restrict__ wr2) {
    extern __shared__ float smemf[];
    uint4*  sKV = (uint4*)smemf;                       // 16KB (permuted order)
    float4* sVC = (float4*)(sKV + NN);                 // 16KB (permuted order)
    unsigned short* sIdx = (unsigned short*)(sVC + NN);// 16KB
    float* sAgg = (float*)(sIdx + 8*NN);               // 32*5 = 640B
    int b   = blockIdx.x >> 5;
    int seg = blockIdx.x & 31;

    {
        const uint4*  t0 = g_kv + b*NN;
        const float4* t1 = g_vc + b*NN;
        for (int i = threadIdx.x; i < NN; i += 256) {
            sKV[i] = t0[i]; sVC[i] = t1[i];
        }
    }
    __syncthreads();

    int lane = threadIdx.x & 31, warp = threadIdx.x >> 5;
    unsigned short* widx = sIdx + warp * NN;
    const int   simple = g_simple;
    const float Cc     = g_C;
    const float bcS    = g_bcShift;
    const unsigned FULL = 0xffffffffu;

    #pragma unroll 1
    for (int r = 0; r < 4; r++) {
        int i   = seg * 32 + warp * 4 + r;    // row within batch
        int row = b * NN + i;

        // ---- stage 1: compact 1-hop bits into smem list (true indices) ----
        const unsigned* bb = g_bits + (size_t)(b*NN)*NWORDS;
        unsigned self = bb[(size_t)i*NWORDS + lane];
        int cnt1 = warp_compact<false>(self, lane, widx);
        __syncwarp(FULL);

        // ---- stage 2: OR 2-hop rows (independent coalesced LDGs) ----
        unsigned acc = self;
        {   // eye bit in permuted bit layout
            int wi = (((i >> 7) << 2) | (i & 3));
            if (lane == wi) acc |= 1u << ((i >> 2) & 31);
        }
        int p = 0;
        #pragma unroll 1
        for (; p + 4 <= cnt1; p += 4) {
            int j0 = (int)widx[p+0], j1 = (int)widx[p+1];
            int j2 = (int)widx[p+2], j3 = (int)widx[p+3];
            unsigned w0 = bb[(size_t)j0*NWORDS + lane];
            unsigned w1 = bb[(size_t)j1*NWORDS + lane];
            unsigned w2 = bb[(size_t)j2*NWORDS + lane];
            unsigned w3 = bb[(size_t)j3*NWORDS + lane];
            acc |= (w0 | w1) | (w2 | w3);
        }
        #pragma unroll 1
        for (; p < cnt1; p++)
            acc |= bb[(size_t)((int)widx[p])*NWORDS + lane];
        __syncwarp(FULL);

        // ---- stage 3: compact 2-hop bits (permuted table positions) ----
        int cnt = warp_compact<true>(acc, lane, widx);
        __syncwarp(FULL);

        // ---- gather + softmax-weighted aggregate ----
        uint4 qh = g_qh[row];
        half2 q01h = *(half2*)&qh.x;
        half2 q23h = *(half2*)&qh.y;
        half2 q45h = *(half2*)&qh.z;
        float4 ci = sVC[(i >> 2) + (i & 3) * 256];   // self at permuted pos
        float cx = ci.y, cy = ci.z, cz = ci.w;

        float s = 0.f;
        float a0 = 0.f, a1 = 0.f, a2 = 0.f, a3 = 0.f, a4 = 0.f;

        #pragma unroll 1
        for (int base = 0; base < cnt; base += 32) {
            int pp = base + lane;
            if (pp < cnt) {
                int j = (int)widx[pp];
                uint4  kv = sKV[j];
                float4 vc = sVC[j];
                // half2 score: (q0k0+q2k2+q4k4, q1k1+q3k3+0)
                half2 acc2 = __hmul2(q01h, *(half2*)&kv.x);
                acc2 = __hfma2(q23h, *(half2*)&kv.y, acc2);
                acc2 = __hfma2(q45h, *(half2*)&kv.z, acc2);
                float sc = bcS + __low2float(acc2) + __high2float(acc2);
                float dx = cx - vc.y, dy = cy - vc.z, dz = cz - vc.w;
                float d2 = fmaf(dx,dx, fmaf(dy,dy, fmaf(dz,dz, 1e-8f)));
                float dist = sqrtapx(d2);
                if (simple) {
                    sc = fmaf(dist, Cc, sc);
                } else {
                    float rb = 0.f;
                    #pragma unroll
                    for (int h = 0; h < RH; h++) {
                        float t = fmaf(dist, __ldg(&wr1[h]), __ldg(&br1[h]));
                        rb = fmaf(fmaxf(t, 0.f), __ldg(&wr2[h]), rb);
                    }
                    sc = fmaf(rb, LOG2E, sc);
                }
                float e = ex2f(sc);
                s += e;
                float  v0  = __high2float(*(half2*)&kv.z);
                float2 v12 = __half22float2(*(half2*)&kv.w);
                float2 v34 = __half22float2(*(half2*)&vc.x);
                a0 = fmaf(e, v0,    a0);
                a1 = fmaf(e, v12.x, a1);
                a2 = fmaf(e, v12.y, a2);
                a3 = fmaf(e, v34.x, a3);
                a4 = fmaf(e, v34.y, a4);
            }
        }
        // plain-sum warp merge (common shift cancels in normalization)
        #pragma unroll
        for (int off = 16; off; off >>= 1) {
            s  += __shfl_xor_sync(FULL, s,  off);
            a0 += __shfl_xor_sync(FULL, a0, off);
            a1 += __shfl_xor_sync(FULL, a1, off);
            a2 += __shfl_xor_sync(FULL, a2, off);
            a3 += __shfl_xor_sync(FULL, a3, off);
            a4 += __shfl_xor_sync(FULL, a4, off);
        }
        if (lane == 0) {
            float inv = 1.f / s;
            float* dst = sAgg + (warp*4 + r)*DD;
            dst[0] = a0*inv; dst[1] = a1*inv; dst[2] = a2*inv;
            dst[3] = a3*inv; dst[4] = a4*inv;
        }
        __syncwarp(FULL);
    }
    __syncthreads();
    if (threadIdx.x < DD) {
        float t = 0.f;
        #pragma unroll 1
        for (int rr = 0; rr < 32; rr++) t += sAgg[rr*DD + threadIdx.x];
        g_part[blockIdx.x*DD + threadIdx.x] = t;   // fixed order -> deterministic
    }
}

// ---------------- head: pool feats + agg partials, Wo, MLP ------------------
// feats pooling vectorized: 4 nodes = 20 floats = exactly 5 float4s, so
// thread t loads floats [20t, 20t+20) with 5 LDG.128 (one pass, 256 threads
// cover all 1024 nodes) and sums components into the 5 buckets with static
// mapping -- 4x fewer LSU ops than the scalar form.
__global__ void k_head(const float* __restrict__ feats,
                       const float* __restrict__ Wo,
                       const float* __restrict__ w1, const float* __restrict__ b1,
                       const float* __restrict__ w2, const float* __restrict__ b2,
                       float* __restrict__ out) {
    int b = blockIdx.x;
    int t = threadIdx.x;              // 256 threads
    int lane = t & 31, warp = t >> 5;
    __shared__ float wsF[8][DD];
    __shared__ float spF[DD], spA[DD], sp[DD];
    __shared__ float sh[128];

    float lf[DD];
    {
        const float4* f4 = (const float4*)(feats + (size_t)b*NN*DD);
        float4 u0 = f4[t*5+0], u1 = f4[t*5+1], u2 = f4[t*5+2];
        float4 u3 = f4[t*5+3], u4 = f4[t*5+4];
        // nodes: {u0.x..u1.x} {u1.y..u2.y} {u2.z..u3.z} {u3.w..u4.w}
        lf[0] = (u0.x + u1.y) + (u2.z + u3.w);
        lf[1] = (u0.y + u1.z) + (u2.w + u4.x);
        lf[2] = (u0.z + u1.w) + (u3.x + u4.y);
        lf[3] = (u0.w + u2.x) + (u3.y + u4.z);
        lf[4] = (u1.x + u2.y) + (u3.z + u4.w);
    }
    float la[DD] = {0.f,0.f,0.f,0.f,0.f};
    if (t < 32) {
        const float* p = g_part + (b*32 + t)*DD;
        #pragma unroll
        for (int d = 0; d < DD; d++) la[d] = p[d];
    }
    #pragma unroll
    for (int off = 16; off; off >>= 1) {
        #pragma unroll
        for (int d = 0; d < DD; d++) {
            lf[d] += __shfl_xor_sync(0xffffffffu, lf[d], off);
            la[d] += __shfl_xor_sync(0xffffffffu, la[d], off);
        }
    }
    if (lane == 0) {
        #pragma unroll
        for (int d = 0; d < DD; d++) wsF[warp][d] = lf[d];
        if (warp == 0) {
            #pragma unroll
            for (int d = 0; d < DD; d++) spA[d] = la[d] * (1.0f/NN);
        }
    }
    __syncthreads();
    if (t < DD) {
        float s = 0.f;
        #pragma unroll
        for (int w = 0; w < 8; w++) s += wsF[w][t];
        spF[t] = s * (1.0f/NN);
    }
    __syncthreads();
    if (t < DD) {
        float o = spF[t];
        #pragma unroll
        for (int d = 0; d < DD; d++) o = fmaf(spA[d], __ldg(&Wo[d*DD + t]), o);
        sp[t] = o;
    }
    __syncthreads();
    if (t < 128) {
        float h = b1[t];
        #pragma unroll
        for (int d = 0; d < DD; d++) h = fmaf(sp[d], w1[d*128 + t], h);
        sh[t] = fmaxf(h, 0.f);
    }
    __syncthreads();
    if (t < 3) {
        float o = b2[t];
        for (int h = 0; h < 128; h++) o = fmaf(sh[h], w2[h*3 + t], o);
        out[b*3 + t] = o;
    }
}

// ---------------- launcher ---------------------------------------------------
extern "C" void kernel_launch(void* const* d_in, const int* in_sizes, int n_in,
                              void* d_out, int out_size) {
    const float* feats = (const float*)d_in[0];
    const float* coors = (const float*)d_in[1];
    const void*  adj   = d_in[2];
    const float* Wq    = (const float*)d_in[3];
    const float* Wk    = (const float*)d_in[4];
    const float* Wv    = (const float*)d_in[5];
    const float* Wo    = (const float*)d_in[6];
    const float* wr1   = (const float*)d_in[7];
    const float* br1   = (const float*)d_in[8];
    const float* wr2   = (const float*)d_in[9];
    const float* br2   = (const float*)d_in[10];
    const float* w1    = (const float*)d_in[11];
    const float* b1    = (const float*)d_in[12];
    const float* w2    = (const float*)d_in[13];
    const float* b2    = (const float*)d_in[14];
    float* out = (float*)d_out;

    const int ATTN_SMEM = 48*1024 + 32*DD*4;   // tables + idx + agg
    cudaFuncSetAttribute(k_attn, cudaFuncAttributeMaxDynamicSharedMemorySize, ATTN_SMEM);

    k_pack_rec<<<PACK_BLOCKS + REC_BLOCKS + 1, 256>>>((const unsigned*)adj, feats, coors,
                                                      Wq, Wk, Wv, wr1, br1, wr2, br2);
    k_attn<<<BB*32, 256, ATTN_SMEM>>>(wr1, br1, wr2);
    k_head<<<BB, 256>>>(feats, Wo, w1, b1, w2, b2, out);
}